// round 9
// baseline (speedup 1.0000x reference)
#include <cuda_runtime.h>
#include <cuda_fp16.h>
#include <math.h>
#include <float.h>

#define B_DIM  256
#define BP     128                      // b-pairs: (b, b+128) share half2 lanes
#define T_DIM  150
#define J_DIM  25
#define FEAT   9
#define NACC   7
#define SPLIT  5
#define TCHUNK (T_DIM / SPLIT)          // 30 timesteps per block
#define ROWS   (TCHUNK / 2)             // 15 thread-rows; chains at r, r+15
#define TPB    (ROWS * J_DIM)           // 375
#define ITEMS  (TCHUNK * J_DIM)         // 750
#define OUTB   (J_DIM * FEAT)           // 225
#define PARTB  (J_DIM * NACC)           // 175

__device__ float    g_scratch[B_DIM][SPLIT][PARTB];
__device__ unsigned g_ticket[B_DIM];    // zero-init; self-resetting

__device__ __forceinline__ float asqrt(float x) {
    float r;
    asm("sqrt.approx.f32 %0, %1;" : "=f"(r) : "f"(x));
    return r;
}

// half2 sorted insert (both lanes independently), branch-free
#define INS4H(g, m0, m1, m2, m3) do {                       \
    __half2 _h;                                             \
    _h = __hmax2(g, m0); m0 = __hmin2(g, m0); g = _h;       \
    _h = __hmax2(g, m1); m1 = __hmin2(g, m1); g = _h;       \
    _h = __hmax2(g, m2); m2 = __hmin2(g, m2); g = _h;       \
    m3 = __hmin2(g, m3);                                    \
} while (0)

__global__ __launch_bounds__(TPB, 4)
void knn_feat_kernel(const float* __restrict__ x, float* __restrict__ out) {
    // [t-row][joint] = {x2,y2,z2,pad}; half2 lanes = (b, b+128) at same t
    __shared__ uint4 sq[TCHUNK][J_DIM];      // 12000 B
    __shared__ float spart[2][PARTB];
    __shared__ float sfin[2][PARTB];
    __shared__ bool  slast[2];

    const int bp  = blockIdx.x;              // 0..127
    const int s   = blockIdx.y;              // 0..4
    const int tid = threadIdx.x;
    const int b0  = bp;
    const int b1  = bp + BP;

    // cooperative load: 30 t x 25 j, two batches packed into half2 lanes
    const float* x0 = x + ((size_t)(b0 * T_DIM + s * TCHUNK)) * (J_DIM * 3);
    const float* x1 = x + ((size_t)(b1 * T_DIM + s * TCHUNK)) * (J_DIM * 3);
#pragma unroll
    for (int rr = 0; rr < 2; ++rr) {
        int i = tid + rr * TPB;              // 0..749 = t*25 + j
        int off = 3 * i;
        __half2 X = __halves2half2(__float2half_rn(x0[off + 0]),
                                   __float2half_rn(x1[off + 0]));
        __half2 Y = __halves2half2(__float2half_rn(x0[off + 1]),
                                   __float2half_rn(x1[off + 1]));
        __half2 Z = __halves2half2(__float2half_rn(x0[off + 2]),
                                   __float2half_rn(x1[off + 2]));
        uint4 v;
        v.x = *(unsigned*)&X; v.y = *(unsigned*)&Y; v.z = *(unsigned*)&Z; v.w = 0;
        sq[i / J_DIM][i % J_DIM] = v;
    }
    if (tid < 2 * PARTB) spart[tid / PARTB][tid % PARTB] = 0.0f;
    __syncthreads();

    const int jidx = tid % J_DIM;
    const int r    = tid / J_DIM;            // 0..14; chains at rows r, r+15

    const unsigned inf_bits = 0x7C007C00u;
    const __half2 inf2 = *(const __half2*)&inf_bits;

    // chain A (t-row r) and chain B (t-row r+15) query positions
    const uint4 PAr = sq[r][jidx];
    const uint4 PBr = sq[r + ROWS][jidx];
    const __half2 pax = *(const __half2*)&PAr.x, pay = *(const __half2*)&PAr.y,
                  paz = *(const __half2*)&PAr.z;
    const __half2 pbx = *(const __half2*)&PBr.x, pby = *(const __half2*)&PBr.y,
                  pbz = *(const __half2*)&PBr.z;

    __half2 a0 = inf2, a1 = inf2, a2 = inf2, a3 = inf2;
    __half2 b0m = inf2, b1m = inf2, b2m = inf2, b3m = inf2;

#pragma unroll
    for (int j = 0; j < J_DIM; ++j) {
        const uint4 QA = sq[r][j];           // broadcast-ish (<=2 addrs/warp)
        const uint4 QB = sq[r + ROWS][j];

        const __half2 qax = *(const __half2*)&QA.x;
        const __half2 qay = *(const __half2*)&QA.y;
        const __half2 qaz = *(const __half2*)&QA.z;
        const __half2 dax = __hsub2(pax, qax);
        const __half2 day = __hsub2(pay, qay);
        const __half2 daz = __hsub2(paz, qaz);
        __half2 ga = __hfma2(dax, dax, __hfma2(day, day, __hmul2(daz, daz)));

        const __half2 qbx = *(const __half2*)&QB.x;
        const __half2 qby = *(const __half2*)&QB.y;
        const __half2 qbz = *(const __half2*)&QB.z;
        const __half2 dbx = __hsub2(pbx, qbx);
        const __half2 dby = __hsub2(pby, qby);
        const __half2 dbz = __hsub2(pbz, qbz);
        __half2 gb = __hfma2(dbx, dbx, __hfma2(dby, dby, __hmul2(dbz, dbz)));

        const bool self = (j == jidx);
        ga = self ? inf2 : ga;
        gb = self ? inf2 : gb;

        INS4H(ga, a0, a1, a2, a3);
        INS4H(gb, b0m, b1m, b2m, b3m);
    }

    // epilogue: 2 chains x 2 halves; half h -> batch index h (b0 lo / b1 hi)
#pragma unroll
    for (int c = 0; c < 2; ++c) {
        const __half2 m0 = c ? b0m : a0;
        const __half2 m1 = c ? b1m : a1;
        const __half2 m2 = c ? b2m : a2;
        const __half2 m3 = c ? b3m : a3;
#pragma unroll
        for (int h = 0; h < 2; ++h) {
            const float q0 = h ? __high2float(m0) : __low2float(m0);
            const float q1 = h ? __high2float(m1) : __low2float(m1);
            const float q2 = h ? __high2float(m2) : __low2float(m2);
            const float q3 = h ? __high2float(m3) : __low2float(m3);

            const float d1 = asqrt(q0);
            const float d2 = asqrt(q1);
            const float d3 = asqrt(q2);
            const float d4 = asqrt(q3);

            const float s2 = fabsf(d2 - d1) * 0.70710678118654752f;
            const float m3f = (d1 + d2 + d3) * (1.0f / 3.0f);
            const float e1 = d1 - m3f, e2 = d2 - m3f, e3 = d3 - m3f;
            const float s3 = asqrt(fmaf(e1, e1, fmaf(e2, e2, e3 * e3)) * 0.5f);
            const float m4f = (d1 + d2 + d3 + d4) * 0.25f;
            const float g1 = d1 - m4f, g2 = d2 - m4f, g3 = d3 - m4f, g4 = d4 - m4f;
            const float s4 = asqrt(fmaf(g1, g1, fmaf(g2, g2, fmaf(g3, g3, g4 * g4)))
                                   * (1.0f / 3.0f));

            float* sp = &spart[h][jidx * NACC];
            atomicAdd(&sp[0], d1);
            atomicAdd(&sp[1], d2);
            atomicAdd(&sp[2], d3);
            atomicAdd(&sp[3], d4);
            atomicAdd(&sp[4], s2);
            atomicAdd(&sp[5], s3);
            atomicAdd(&sp[6], s4);
        }
    }
    __syncthreads();

    // publish both b's partials
    if (tid < PARTB) {
        g_scratch[b0][s][tid] = spart[0][tid];
        g_scratch[b1][s][tid] = spart[1][tid];
    }
    __threadfence();
    __syncthreads();

    if (tid == 0) {
        unsigned o0 = atomicAdd(&g_ticket[b0], 1u);
        slast[0] = (o0 == SPLIT - 1);
        if (slast[0]) g_ticket[b0] = 0;
    }
    if (tid == 1) {
        unsigned o1 = atomicAdd(&g_ticket[b1], 1u);
        slast[1] = (o1 == SPLIT - 1);
        if (slast[1]) g_ticket[b1] = 0;
    }
    __syncthreads();

#pragma unroll
    for (int w = 0; w < 2; ++w) {
        if (slast[w]) {
            const int bb = w ? b1 : b0;
            __threadfence();
            if (tid < PARTB) {
                float sum = 0.0f;
#pragma unroll
                for (int k = 0; k < SPLIT; ++k)
                    sum += g_scratch[bb][k][tid];
                sfin[w][tid] = sum;
            }
            __syncthreads();
            if (tid < OUTB) {
                const int j = tid / FEAT;
                const int f = tid % FEAT;
                const float* a = &sfin[w][j * NACC];
                const float t1 = a[0], t2 = a[1], t3 = a[2], t4 = a[3];
                float v;
                switch (f) {
                    case 0: v = (t1 + t2) * 0.5f;               break;
                    case 1: v = a[4];                           break;
                    case 2: v = t1;                             break;
                    case 3: v = (t1 + t2 + t3) * (1.f / 3.f);   break;
                    case 4: v = a[5];                           break;
                    case 5: v = t1;                             break;
                    case 6: v = (t1 + t2 + t3 + t4) * 0.25f;    break;
                    case 7: v = a[6];                           break;
                    default: v = t1;                            break;
                }
                out[(size_t)bb * OUTB + tid] = v * (1.0f / (float)T_DIM);
            }
        }
    }
}

extern "C" void kernel_launch(void* const* d_in, const int* in_sizes, int n_in,
                              void* d_out, int out_size) {
    const float* x = (const float*)d_in[0];
    float* out = (float*)d_out;
    dim3 grid(BP, SPLIT);
    knn_feat_kernel<<<grid, TPB>>>(x, out);
}

// round 10
// speedup vs baseline: 1.1172x; 1.1172x over previous
#include <cuda_runtime.h>
#include <cuda_fp16.h>
#include <math.h>
#include <float.h>

#define B_DIM  256
#define T_DIM  150
#define J_DIM  25
#define FEAT   9
#define NACC   7
#define SPLIT  5
#define TCHUNK (T_DIM / SPLIT)          // 30 timesteps per block
#define NPAIR  (TCHUNK / 2)             // 15 timestep-pairs
#define ACTIVE (NPAIR * J_DIM)          // 375 compute threads
#define TPB    384                      // 12 full warps
#define ITEMS  (TCHUNK * J_DIM)         // 750
#define OUTB   (J_DIM * FEAT)           // 225
#define PARTB  (J_DIM * NACC)           // 175

__device__ float    g_scratch[B_DIM][SPLIT][PARTB];
__device__ unsigned g_ticket[B_DIM];    // zero-init; self-resetting

__device__ __forceinline__ float asqrt(float x) {
    float r;
    asm("sqrt.approx.f32 %0, %1;" : "=f"(r) : "f"(x));
    return r;
}

__global__ __launch_bounds__(TPB, 4)
void knn_feat_kernel(const float* __restrict__ x, float* __restrict__ out) {
    // packed positions: [pair][joint] = {x2, y2, z2, pad} (half2 lanes = t, t+15)
    __shared__ uint4 sq[NPAIR][J_DIM];       // 6000 B
    __shared__ float spart[PARTB];
    __shared__ float sfin[PARTB];
    __shared__ bool  s_last;

    const int b   = blockIdx.x;
    const int s   = blockIdx.y;
    const int tid = threadIdx.x;

    // build packed half2 SMEM tile
    const float* xb = x + ((size_t)b * T_DIM + s * TCHUNK) * (J_DIM * 3);
#pragma unroll
    for (int r = 0; r < 2; ++r) {
        int i = tid + r * TPB;               // 0..749 : (t, j) item
        if (i < ITEMS) {
            int t = i / J_DIM;
            int j = i % J_DIM;
            int pr = t % NPAIR;
            int hi = t / NPAIR;
            __half hx = __float2half_rn(xb[3 * i + 0]);
            __half hy = __float2half_rn(xb[3 * i + 1]);
            __half hz = __float2half_rn(xb[3 * i + 2]);
            __half* base = (__half*)&sq[pr][j];
            base[0 * 2 + hi] = hx;
            base[1 * 2 + hi] = hy;
            base[2 * 2 + hi] = hz;
        }
    }
    if (tid < PARTB) spart[tid] = 0.0f;
    __syncthreads();

    if (tid < ACTIVE) {
        const int jidx = tid % J_DIM;        // this thread's joint
        const int pr   = tid / J_DIM;        // timestep pair (0..14)

        // query position (both halves) — one LDS.128
        const uint4 P = sq[pr][jidx];
        const __half2 px = *(const __half2*)&P.x;
        const __half2 py = *(const __half2*)&P.y;
        const __half2 pz = *(const __half2*)&P.z;

        const unsigned inf_bits = 0x7C007C00u;   // (+inf, +inf)
        const __half2 inf2 = *(const __half2*)&inf_bits;

        __half2 m0 = inf2, m1 = inf2, m2 = inf2, m3 = inf2;

        // double-buffered candidate loop: load j+1 before processing j
        uint4 Q = sq[pr][0];
#pragma unroll
        for (int j = 0; j < J_DIM; ++j) {
            const uint4 Qn = (j + 1 < J_DIM) ? sq[pr][j + 1] : Q;

            const __half2 qx = *(const __half2*)&Q.x;
            const __half2 qy = *(const __half2*)&Q.y;
            const __half2 qz = *(const __half2*)&Q.z;

            const __half2 dx = __hsub2(px, qx);
            const __half2 dy = __hsub2(py, qy);
            const __half2 dz = __hsub2(pz, qz);
            __half2 g = __hfma2(dx, dx, __hfma2(dy, dy, __hmul2(dz, dz)));
            g = (j == jidx) ? inf2 : g;          // mask self (both halves)

            __half2 h;
            h = __hmax2(g, m0); m0 = __hmin2(g, m0); g = h;
            h = __hmax2(g, m1); m1 = __hmin2(g, m1); g = h;
            h = __hmax2(g, m2); m2 = __hmin2(g, m2); g = h;
            m3 = __hmin2(g, m3);

            Q = Qn;
        }

        // epilogue: two chains (lo/hi halves), features in fp32, summed
        float S1 = 0.f, S2 = 0.f, S3 = 0.f, S4 = 0.f;
        float V2 = 0.f, V3 = 0.f, V4 = 0.f;

#pragma unroll
        for (int h = 0; h < 2; ++h) {
            const float q0 = h ? __high2float(m0) : __low2float(m0);
            const float q1 = h ? __high2float(m1) : __low2float(m1);
            const float q2 = h ? __high2float(m2) : __low2float(m2);
            const float q3 = h ? __high2float(m3) : __low2float(m3);

            const float d1 = asqrt(q0);
            const float d2 = asqrt(q1);
            const float d3 = asqrt(q2);
            const float d4 = asqrt(q3);

            const float s2 = fabsf(d2 - d1) * 0.70710678118654752f;
            const float a3 = (d1 + d2 + d3) * (1.0f / 3.0f);
            const float e1 = d1 - a3, e2 = d2 - a3, e3 = d3 - a3;
            const float s3 = asqrt(fmaf(e1, e1, fmaf(e2, e2, e3 * e3)) * 0.5f);
            const float a4 = (d1 + d2 + d3 + d4) * 0.25f;
            const float g1 = d1 - a4, g2 = d2 - a4, g3 = d3 - a4, g4 = d4 - a4;
            const float s4 = asqrt(fmaf(g1, g1, fmaf(g2, g2, fmaf(g3, g3, g4 * g4)))
                                   * (1.0f / 3.0f));

            S1 += d1; S2 += d2; S3 += d3; S4 += d4;
            V2 += s2; V3 += s3; V4 += s4;
        }

        // combine the 15 threads sharing each joint (SMEM atomics)
        atomicAdd(&spart[jidx * NACC + 0], S1);
        atomicAdd(&spart[jidx * NACC + 1], S2);
        atomicAdd(&spart[jidx * NACC + 2], S3);
        atomicAdd(&spart[jidx * NACC + 3], S4);
        atomicAdd(&spart[jidx * NACC + 4], V2);
        atomicAdd(&spart[jidx * NACC + 5], V3);
        atomicAdd(&spart[jidx * NACC + 6], V4);
    }
    __syncthreads();

    // publish this split's partial
    if (tid < PARTB) g_scratch[b][s][tid] = spart[tid];
    __threadfence();
    __syncthreads();

    if (tid == 0) {
        unsigned old = atomicAdd(&g_ticket[b], 1u);
        s_last = (old == SPLIT - 1);
        if (s_last) g_ticket[b] = 0;   // self-reset for next graph replay
    }
    __syncthreads();

    if (s_last) {
        __threadfence();
        if (tid < PARTB) {
            float sum = 0.0f;
#pragma unroll
            for (int k = 0; k < SPLIT; ++k)
                sum += g_scratch[b][k][tid];
            sfin[tid] = sum;
        }
        __syncthreads();
        if (tid < OUTB) {
            const int j = tid / FEAT;
            const int f = tid % FEAT;
            const float* a = &sfin[j * NACC];
            const float t1 = a[0], t2 = a[1], t3 = a[2], t4 = a[3];
            float v;
            switch (f) {
                case 0: v = (t1 + t2) * 0.5f;               break;
                case 1: v = a[4];                           break;
                case 2: v = t1;                             break;
                case 3: v = (t1 + t2 + t3) * (1.f / 3.f);   break;
                case 4: v = a[5];                           break;
                case 5: v = t1;                             break;
                case 6: v = (t1 + t2 + t3 + t4) * 0.25f;    break;
                case 7: v = a[6];                           break;
                default: v = t1;                            break;
            }
            out[(size_t)b * OUTB + tid] = v * (1.0f / (float)T_DIM);
        }
    }
}

extern "C" void kernel_launch(void* const* d_in, const int* in_sizes, int n_in,
                              void* d_out, int out_size) {
    const float* x = (const float*)d_in[0];
    float* out = (float*)d_out;
    dim3 grid(B_DIM, SPLIT);
    knn_feat_kernel<<<grid, TPB>>>(x, out);
}